// round 3
// baseline (speedup 1.0000x reference)
#include <cuda_runtime.h>
#include <math.h>
#include <stdint.h>

// Problem constants (fixed by the dataset)
#define BB 2
#define NN 50000
#define DD 128
#define EE 500000
#define ROWS (BB * NN)          // 100000 node-rows total

// Scratch (static device globals — no runtime allocation)
__device__ float g_hm[ROWS * DD];   // h @ msg_W            (51.2 MB)
__device__ float g_hg[ROWS * DD];   // sigmoid(h @ gate_W)  (51.2 MB)
__device__ float g_agg[ROWS * DD];  // scatter-add target   (51.2 MB)

// ---------------------------------------------------------------------------
// tf32 mma helpers
// ---------------------------------------------------------------------------
__device__ __forceinline__ uint32_t f2tf32(float x) {
    uint32_t r;
    asm("cvt.rna.tf32.f32 %0, %1;" : "=r"(r) : "f"(x));
    return r;
}

__device__ __forceinline__ void mma_tf32(float c[4], const uint32_t a[4],
                                         const uint32_t b[2]) {
    asm volatile(
        "mma.sync.aligned.m16n8k8.row.col.f32.tf32.tf32.f32 "
        "{%0,%1,%2,%3}, {%4,%5,%6,%7}, {%8,%9}, {%0,%1,%2,%3};"
        : "+f"(c[0]), "+f"(c[1]), "+f"(c[2]), "+f"(c[3])
        : "r"(a[0]), "r"(a[1]), "r"(a[2]), "r"(a[3]), "r"(b[0]), "r"(b[1]));
}

// Fragment-permuted smem layouts (we control the writer, so store tiles in
// exactly the per-lane fragment order; frag loads become LDS.128 / LDS.64):
//  A tile (16m x 8k):  Ap[mtile][ktile][lane][4]   a0..a3 per PTX m16n8k8 row
//  B tile (8k x 8n):   Bp[ktile][ntile][lane][2]   b0..b1 per PTX col
// Per-element mapping:
//  A(m,k): lane = (m%8)*4 + (k%4); slot = ((k%8)>=4)*2 + ((m%16)>=8)
//  B(k,n): lane = (n%8)*4 + (k%4); slot = ((k%8)>=4)

#define NODE_SMEM  (8 * 16 * 128 * 4 + 16 * 16 * 64 * 4)            // 131072 B
#define UPD_XWORDS (128 * 132)                                       // 16896
#define UPD_SMEM   ((UPD_XWORDS + 32 * 16 * 64) * 4)                 // 198656 B

// ---------------------------------------------------------------------------
// Kernel 1: hm = h @ msg_W ; hg = sigmoid(h @ gate_W)   (tf32 tensor GEMM)
// grid = (782, 2): y=0 -> msg_W -> g_hm, y=1 -> gate_W -> g_hg
// Block tile 128x128, K=128. 512 threads = 4x4 warps, warp tile 32x32.
// ---------------------------------------------------------------------------
__global__ __launch_bounds__(512) void node_pre_mma(
    const float* __restrict__ h,
    const float* __restrict__ msg_W,
    const float* __restrict__ gate_W)
{
    extern __shared__ uint32_t sh[];
    uint32_t* Ap = sh;                 // [8][16][32][4] = 16384 words
    uint32_t* Bp = sh + 8 * 16 * 128;  // [16][16][32][2] = 16384 words

    const int tid = threadIdx.x;
    const int m0  = blockIdx.x * 128;
    const float* W = blockIdx.y ? gate_W : msg_W;

    // ---- B permute (W[k][n], 128x128) ----
    {
        const float4* W4 = (const float4*)W;
        for (int i = tid; i < 128 * 32; i += 512) {
            int k = i >> 5, n = (i & 31) * 4;
            float4 v = W4[i];
            int kt = k >> 3, slot = (k >> 2) & 1, kl = k & 3;
            float vv[4] = {v.x, v.y, v.z, v.w};
#pragma unroll
            for (int j = 0; j < 4; j++) {
                int nn = n + j;
                int lane = ((nn & 7) << 2) | kl;
                Bp[((((kt << 4) | (nn >> 3)) << 5) + lane) * 2 + slot] = f2tf32(vv[j]);
            }
        }
    }
    // ---- A permute (h[m0+m][k]) ----
    {
        const float4* h4 = (const float4*)h;
        for (int i = tid; i < 128 * 32; i += 512) {
            int m = i >> 5, k = (i & 31) * 4;
            int row = m0 + m;
            float4 v = (row < ROWS) ? h4[row * 32 + (k >> 2)]
                                    : make_float4(0.f, 0.f, 0.f, 0.f);
            int mt = m >> 4, lane_hi = (m & 7) << 2;
            int sm = (m & 15) >> 3;
            float vv[4] = {v.x, v.y, v.z, v.w};
#pragma unroll
            for (int j = 0; j < 4; j++) {
                int kk = k + j;
                int kt = kk >> 3;
                int slot = ((((kk & 7) >> 2) << 1) | sm);
                int lane = lane_hi | (kk & 3);
                Ap[((((mt << 4) | kt) << 5) + lane) * 4 + slot] = f2tf32(vv[j]);
            }
        }
    }
    __syncthreads();

    const int wid = tid >> 5, lane = tid & 31;
    const int wm = wid >> 2, wn = wid & 3;

    float acc[2][4][4];
#pragma unroll
    for (int mt = 0; mt < 2; mt++)
#pragma unroll
        for (int nt = 0; nt < 4; nt++)
#pragma unroll
            for (int q = 0; q < 4; q++) acc[mt][nt][q] = 0.f;

    const uint32_t* Ap0 = Ap + (((wm * 2 + 0) * 16) << 7) + (lane << 2);
    const uint32_t* Ap1 = Ap + (((wm * 2 + 1) * 16) << 7) + (lane << 2);
    const uint32_t* Bpw = Bp + ((wn * 4) << 6) + (lane << 1);

#pragma unroll
    for (int ks = 0; ks < 16; ks++) {
        uint4 a0 = *(const uint4*)(Ap0 + (ks << 7));
        uint4 a1 = *(const uint4*)(Ap1 + (ks << 7));
        uint32_t af[2][4] = {{a0.x, a0.y, a0.z, a0.w}, {a1.x, a1.y, a1.z, a1.w}};
        uint2 bv[4];
#pragma unroll
        for (int nt = 0; nt < 4; nt++)
            bv[nt] = *(const uint2*)(Bpw + ((ks << 10) + (nt << 6)));
#pragma unroll
        for (int mt = 0; mt < 2; mt++)
#pragma unroll
            for (int nt = 0; nt < 4; nt++) {
                uint32_t bf[2] = {bv[nt].x, bv[nt].y};
                mma_tf32(acc[mt][nt], af[mt], bf);
            }
    }

    // Epilogue: c0,c1 -> (r, c2); c2,c3 -> (r+8, c2)
    const bool isGate = (blockIdx.y != 0);
    float* dst = isGate ? g_hg : g_hm;
    const int r  = lane >> 2;
    const int c2 = (lane & 3) * 2;
#pragma unroll
    for (int mt = 0; mt < 2; mt++) {
#pragma unroll
        for (int nt = 0; nt < 4; nt++) {
            int row = m0 + wm * 32 + mt * 16 + r;
            int col = wn * 32 + nt * 8 + c2;
            float v0 = acc[mt][nt][0], v1 = acc[mt][nt][1];
            float v2 = acc[mt][nt][2], v3 = acc[mt][nt][3];
            if (isGate) {
                v0 = 1.f / (1.f + __expf(-v0));
                v1 = 1.f / (1.f + __expf(-v1));
                v2 = 1.f / (1.f + __expf(-v2));
                v3 = 1.f / (1.f + __expf(-v3));
            }
            if (row < ROWS)
                *(float2*)&dst[row * DD + col] = make_float2(v0, v1);
            if (row + 8 < ROWS)
                *(float2*)&dst[(row + 8) * DD + col] = make_float2(v2, v3);
        }
    }
}

// ---------------------------------------------------------------------------
// Kernel 2: edge scatter. One warp per edge; both batches.
//   agg[b, tgt] += hm[b, src] * rel_emb[rel] * hg[b, src]
// ---------------------------------------------------------------------------
__global__ __launch_bounds__(256) void edge_scatter_kernel(
    const int* __restrict__ esrc,
    const int* __restrict__ etgt,
    const int* __restrict__ erel,
    const float* __restrict__ rel_emb)
{
    const int gw   = (blockIdx.x * blockDim.x + threadIdx.x) >> 5;
    const int lane = threadIdx.x & 31;
    if (gw >= EE) return;

    const int s = esrc[gw];
    const int t = etgt[gw];
    const int r = erel[gw];

    const float4* R4 = (const float4*)rel_emb;
    const float4  rv = R4[r * 32 + lane];
    const float4* HM = (const float4*)g_hm;
    const float4* HG = (const float4*)g_hg;
    float*        AG = g_agg;

#pragma unroll
    for (int b = 0; b < BB; b++) {
        int idx = (b * NN + s) * 32 + lane;
        float4 m = HM[idx];
        float4 g = HG[idx];
        float4 o;
        o.x = m.x * rv.x * g.x;
        o.y = m.y * rv.y * g.y;
        o.z = m.z * rv.z * g.z;
        o.w = m.w * rv.w * g.w;
        float* p = &AG[((b * NN + t) * 32 + lane) * 4];
        asm volatile("red.global.add.v4.f32 [%0], {%1, %2, %3, %4};"
                     :: "l"(p), "f"(o.x), "f"(o.y), "f"(o.z), "f"(o.w)
                     : "memory");
    }
}

// ---------------------------------------------------------------------------
// Kernel 3: upd = [h | agg] @ update_W + b ; x = h + relu(upd) ; out = LN(x)
// tf32 tensor GEMM, M tile 128, N=128, K=256 (2 stages of 128).
// 512 threads = 4x4 warps, warp tile 32x32.
// ---------------------------------------------------------------------------
__global__ __launch_bounds__(512) void update_ln_mma(
    const float* __restrict__ h,
    const float* __restrict__ update_W,
    const float* __restrict__ update_b,
    const float* __restrict__ ln_gamma,
    const float* __restrict__ ln_beta,
    float* __restrict__ out)
{
    extern __shared__ uint32_t sh[];
    uint32_t* Ap  = sh;                 // [8][16][32][4] = 16384 words (first part of X region)
    float*    Xsh = (float*)sh;         // [128][132] = 16896 words (reused after GEMM)
    uint32_t* Bp  = sh + UPD_XWORDS;    // [32][16][32][2] = 32768 words

    const int tid = threadIdx.x;
    const int m0  = blockIdx.x * 128;

    // ---- B permute (update_W[k][n], 256x128) ----
    {
        const float4* W4 = (const float4*)update_W;
        for (int i = tid; i < 256 * 32; i += 512) {
            int k = i >> 5, n = (i & 31) * 4;
            float4 v = W4[i];
            int kt = k >> 3, slot = (k >> 2) & 1, kl = k & 3;
            float vv[4] = {v.x, v.y, v.z, v.w};
#pragma unroll
            for (int j = 0; j < 4; j++) {
                int nn = n + j;
                int lane = ((nn & 7) << 2) | kl;
                Bp[((((kt << 4) | (nn >> 3)) << 5) + lane) * 2 + slot] = f2tf32(vv[j]);
            }
        }
    }

    const int wid = tid >> 5, lane = tid & 31;
    const int wm = wid >> 2, wn = wid & 3;

    float acc[2][4][4];
#pragma unroll
    for (int mt = 0; mt < 2; mt++)
#pragma unroll
        for (int nt = 0; nt < 4; nt++)
#pragma unroll
            for (int q = 0; q < 4; q++) acc[mt][nt][q] = 0.f;

    const uint32_t* Ap0 = Ap + (((wm * 2 + 0) * 16) << 7) + (lane << 2);
    const uint32_t* Ap1 = Ap + (((wm * 2 + 1) * 16) << 7) + (lane << 2);
    const uint32_t* Bpw = Bp + ((wn * 4) << 6) + (lane << 1);

    for (int s = 0; s < 2; s++) {
        if (s) __syncthreads();   // all warps done reading stage-0 Ap
        // ---- A permute: stage 0 = h, stage 1 = g_agg ----
        {
            const float4* src4 = (const float4*)(s ? g_agg : h);
            for (int i = tid; i < 128 * 32; i += 512) {
                int m = i >> 5, k = (i & 31) * 4;
                int row = m0 + m;
                float4 v = (row < ROWS) ? src4[row * 32 + (k >> 2)]
                                        : make_float4(0.f, 0.f, 0.f, 0.f);
                int mt = m >> 4, lane_hi = (m & 7) << 2;
                int sm = (m & 15) >> 3;
                float vv[4] = {v.x, v.y, v.z, v.w};
#pragma unroll
                for (int j = 0; j < 4; j++) {
                    int kk = k + j;
                    int kt = kk >> 3;
                    int slot = ((((kk & 7) >> 2) << 1) | sm);
                    int lane2 = lane_hi | (kk & 3);
                    Ap[((((mt << 4) | kt) << 5) + lane2) * 4 + slot] = f2tf32(vv[j]);
                }
            }
        }
        __syncthreads();

        const uint32_t* Bstage = Bpw + (s << 14);   // + s*16*16*64
#pragma unroll
        for (int ks = 0; ks < 16; ks++) {
            uint4 a0 = *(const uint4*)(Ap0 + (ks << 7));
            uint4 a1 = *(const uint4*)(Ap1 + (ks << 7));
            uint32_t af[2][4] = {{a0.x, a0.y, a0.z, a0.w},
                                 {a1.x, a1.y, a1.z, a1.w}};
            uint2 bv[4];
#pragma unroll
            for (int nt = 0; nt < 4; nt++)
                bv[nt] = *(const uint2*)(Bstage + ((ks << 10) + (nt << 6)));
#pragma unroll
            for (int mt = 0; mt < 2; mt++)
#pragma unroll
                for (int nt = 0; nt < 4; nt++) {
                    uint32_t bf[2] = {bv[nt].x, bv[nt].y};
                    mma_tf32(acc[mt][nt], af[mt], bf);
                }
        }
    }

    // Epilogue: Xsh = relu(acc + bias)   (residual h added in LN pass, coalesced)
    __syncthreads();
    {
        const int r  = lane >> 2;
        const int c2 = (lane & 3) * 2;
#pragma unroll
        for (int mt = 0; mt < 2; mt++) {
#pragma unroll
            for (int nt = 0; nt < 4; nt++) {
                int rr  = wm * 32 + mt * 16 + r;
                int col = wn * 32 + nt * 8 + c2;
                float b0 = __ldg(&update_b[col]);
                float b1 = __ldg(&update_b[col + 1]);
                float v0 = fmaxf(acc[mt][nt][0] + b0, 0.f);
                float v1 = fmaxf(acc[mt][nt][1] + b1, 0.f);
                float v2 = fmaxf(acc[mt][nt][2] + b0, 0.f);
                float v3 = fmaxf(acc[mt][nt][3] + b1, 0.f);
                *(float2*)&Xsh[rr * 132 + col]       = make_float2(v0, v1);
                *(float2*)&Xsh[(rr + 8) * 132 + col] = make_float2(v2, v3);
            }
        }
    }
    __syncthreads();

    // LayerNorm: 16 warps x 8 rows each; residual added here (coalesced h read)
    {
        const float4 gm = ((const float4*)ln_gamma)[lane];
        const float4 bt = ((const float4*)ln_beta)[lane];
        const float4* h4 = (const float4*)h;
        for (int rr = wid; rr < 128; rr += 16) {
            int row = m0 + rr;
            if (row >= ROWS) continue;
            float4 xv = *(const float4*)&Xsh[rr * 132 + lane * 4];
            float4 hv = h4[row * 32 + lane];
            float4 x = make_float4(xv.x + hv.x, xv.y + hv.y,
                                   xv.z + hv.z, xv.w + hv.w);
            float sum = x.x + x.y + x.z + x.w;
            float sq  = x.x * x.x + x.y * x.y + x.z * x.z + x.w * x.w;
#pragma unroll
            for (int off = 16; off; off >>= 1) {
                sum += __shfl_xor_sync(0xffffffffu, sum, off);
                sq  += __shfl_xor_sync(0xffffffffu, sq, off);
            }
            float mu  = sum * (1.f / 128.f);
            float var = sq * (1.f / 128.f) - mu * mu;
            float inv = rsqrtf(var + 1e-5f);
            float4 o;
            o.x = (x.x - mu) * inv * gm.x + bt.x;
            o.y = (x.y - mu) * inv * gm.y + bt.y;
            o.z = (x.z - mu) * inv * gm.z + bt.z;
            o.w = (x.w - mu) * inv * gm.w + bt.w;
            ((float4*)out)[row * 32 + lane] = o;
        }
    }
}

// ---------------------------------------------------------------------------
extern "C" void kernel_launch(void* const* d_in, const int* in_sizes, int n_in,
                              void* d_out, int out_size)
{
    const float* h        = (const float*)d_in[0];
    const int*   esrc     = (const int*)d_in[1];
    const int*   etgt     = (const int*)d_in[2];
    const int*   erel     = (const int*)d_in[3];
    // d_in[4] = nE (== NN, unused)
    const float* msg_W    = (const float*)d_in[5];
    const float* rel_emb  = (const float*)d_in[6];
    const float* gate_W   = (const float*)d_in[7];
    const float* update_W = (const float*)d_in[8];
    const float* update_b = (const float*)d_in[9];
    const float* gamma    = (const float*)d_in[10];
    const float* beta     = (const float*)d_in[11];
    float*       out      = (float*)d_out;

    cudaFuncSetAttribute(node_pre_mma,
                         cudaFuncAttributeMaxDynamicSharedMemorySize, NODE_SMEM);
    cudaFuncSetAttribute(update_ln_mma,
                         cudaFuncAttributeMaxDynamicSharedMemorySize, UPD_SMEM);

    // Zero the scatter-add target
    void* agg_ptr = nullptr;
    cudaGetSymbolAddress(&agg_ptr, g_agg);
    cudaMemsetAsync(agg_ptr, 0, sizeof(float) * ROWS * DD, 0);

    const int gemm_blocks = (ROWS + 127) / 128;   // 782

    node_pre_mma<<<dim3(gemm_blocks, 2), 512, NODE_SMEM>>>(h, msg_W, gate_W);

    {
        long long total_threads = (long long)EE * 32;
        int blocks = (int)((total_threads + 255) / 256);   // 62500
        edge_scatter_kernel<<<blocks, 256>>>(esrc, etgt, erel, rel_emb);
    }

    update_ln_mma<<<gemm_blocks, 512, UPD_SMEM>>>(h, update_W, update_b,
                                                  gamma, beta, out);
}

// round 5
// speedup vs baseline: 3.1579x; 3.1579x over previous
#include <cuda_runtime.h>
#include <math.h>
#include <stdint.h>

// Problem constants (fixed by the dataset)
#define BB 2
#define NN 50000
#define DD 128
#define EE 500000
#define ROWS (BB * NN)          // 100000 node-rows

// Scratch (static device globals — no runtime allocation)
__device__ __align__(16) float    g_p[ROWS * DD];    // (h@msg_W)*sigmoid(h@gate_W)  51.2MB
__device__ __align__(16) float    g_agg[ROWS * DD];  // scatter-add target           51.2MB
__device__ __align__(16) uint32_t g_Bp_msg[16 * 16 * 32 * 2];   // permuted msg_W   64KB
__device__ __align__(16) uint32_t g_Bp_gate[16 * 16 * 32 * 2];  // permuted gate_W  64KB
__device__ __align__(16) uint32_t g_Bp_upd[32 * 16 * 32 * 2];   // permuted update_W 128KB

// ---------------------------------------------------------------------------
// tf32 mma helpers
// ---------------------------------------------------------------------------
__device__ __forceinline__ uint32_t f2tf32(float x) {
    uint32_t r;
    asm("cvt.rna.tf32.f32 %0, %1;" : "=r"(r) : "f"(x));
    return r;
}

__device__ __forceinline__ void mma_tf32(float c[4], const uint32_t a[4],
                                         const uint32_t b[2]) {
    asm volatile(
        "mma.sync.aligned.m16n8k8.row.col.f32.tf32.tf32.f32 "
        "{%0,%1,%2,%3}, {%4,%5,%6,%7}, {%8,%9}, {%0,%1,%2,%3};"
        : "+f"(c[0]), "+f"(c[1]), "+f"(c[2]), "+f"(c[3])
        : "r"(a[0]), "r"(a[1]), "r"(a[2]), "r"(a[3]), "r"(b[0]), "r"(b[1]));
}

// Shared layout (both GEMM kernels):
//   Ash: row-major fp32(tf32-rounded) [64][132]  = 8448 floats (33792 B)
//   Bs : fragment-permuted [16 kt][16 nt][32 lane][2 slot] = 16384 words (65536 B)
#define ASH_WORDS (64 * 132)
#define GEMM_SMEM ((ASH_WORDS + 16384) * 4)     // 99328 B -> 2 CTAs/SM

// ---------------------------------------------------------------------------
// Setup: permute weights into mma B-fragment order (runs once per launch).
// B(k,n): lane = ((n&7)<<2)|(k&3); slot = (k>>2)&1; word = ((kt*16+nt)*32+lane)*2+slot
// ---------------------------------------------------------------------------
__global__ void permute_W_kernel(const float* __restrict__ msg_W,
                                 const float* __restrict__ gate_W,
                                 const float* __restrict__ upd_W)
{
    const int job = blockIdx.x;
    const int tid = threadIdx.x;
    const float* src;
    uint32_t* dst;
    if (job == 0)      { src = msg_W;                  dst = g_Bp_msg; }
    else if (job == 1) { src = gate_W;                 dst = g_Bp_gate; }
    else               { src = upd_W + (job - 2) * 128 * 128;
                         dst = g_Bp_upd + (job - 2) * 16384; }

    const float4* W4 = (const float4*)src;
    for (int i = tid; i < 128 * 32; i += 256) {
        int k = i >> 5, n4 = (i & 31) * 4;
        float4 v = W4[i];
        float vv[4] = {v.x, v.y, v.z, v.w};
        int kt = k >> 3, slot = (k >> 2) & 1, kl = k & 3;
#pragma unroll
        for (int j = 0; j < 4; j++) {
            int nn = n4 + j;
            int lane = ((nn & 7) << 2) | kl;
            dst[((((kt << 4) | (nn >> 3)) << 5) | lane) * 2 + slot] = f2tf32(vv[j]);
        }
    }
}

// ---------------------------------------------------------------------------
// Mainloop: warp tile 32x32 over K=128 (16 k-steps of 8).
// A frags: scalar LDS from row-major Ash (conflict-free: 132 % 32 == 4).
// B frags: LDS.64 from permuted Bs (conflict-free).
// ---------------------------------------------------------------------------
__device__ __forceinline__ void mma_mainloop(
    const float* __restrict__ A0, const uint32_t* __restrict__ Bw,
    float (&acc)[2][4][4])
{
#pragma unroll
    for (int ks = 0; ks < 16; ks++) {
        uint32_t af[2][4];
#pragma unroll
        for (int mt = 0; mt < 2; mt++) {
            const float* ap = A0 + mt * 2112 + ks * 8;   // 2112 = 16*132
            af[mt][0] = __float_as_uint(ap[0]);
            af[mt][1] = __float_as_uint(ap[1056]);        // +8 rows
            af[mt][2] = __float_as_uint(ap[4]);           // +4 k
            af[mt][3] = __float_as_uint(ap[1060]);
        }
#pragma unroll
        for (int nt = 0; nt < 4; nt++) {
            uint2 bv = *(const uint2*)(Bw + ks * 1024 + nt * 64);
            uint32_t bf[2] = {bv.x, bv.y};
            mma_tf32(acc[0][nt], af[0], bf);
            mma_tf32(acc[1][nt], af[1], bf);
        }
    }
}

// Coalesced A-tile fill: h-like source [ROWS][128] -> Ash[64][132] (tf32-rounded)
__device__ __forceinline__ void fill_A(float* Ash, const float4* __restrict__ src4,
                                       int m0, int tid)
{
#pragma unroll
    for (int it = 0; it < 8; it++) {
        int i = tid + it * 256;
        int m = i >> 5, c = i & 31;
        int row = m0 + m;
        float4 v = (row < ROWS) ? src4[row * 32 + c]
                                : make_float4(0.f, 0.f, 0.f, 0.f);
        uint4 t;
        t.x = f2tf32(v.x); t.y = f2tf32(v.y);
        t.z = f2tf32(v.z); t.w = f2tf32(v.w);
        *(uint4*)&Ash[m * 132 + c * 4] = t;
    }
}

// ---------------------------------------------------------------------------
// Kernel 1: p = (h @ msg_W) * sigmoid(h @ gate_W)
// One CTA = 64-row tile. 256 threads = 2x4 warps, warp tile 32x32.
// Two B stages (msg, gate) share the A tile.
// ---------------------------------------------------------------------------
__global__ __launch_bounds__(256, 2) void node_p_mma(const float* __restrict__ h)
{
    extern __shared__ uint32_t sh[];
    float*    Ash = (float*)sh;       // [64][132]
    uint32_t* Bs  = sh + ASH_WORDS;   // 16384 words

    const int tid  = threadIdx.x;
    const int m0   = blockIdx.x * 64;
    const int lane = tid & 31, wid = tid >> 5;
    const int wm = wid >> 2, wn = wid & 3;

    fill_A(Ash, (const float4*)h, m0, tid);

    float accM[2][4][4], accG[2][4][4];
#pragma unroll
    for (int mt = 0; mt < 2; mt++)
#pragma unroll
        for (int nt = 0; nt < 4; nt++)
#pragma unroll
            for (int q = 0; q < 4; q++) { accM[mt][nt][q] = 0.f; accG[mt][nt][q] = 0.f; }

    const float*    A0 = Ash + (wm * 32 + (lane >> 2)) * 132 + (lane & 3);
    const uint32_t* Bw = Bs + ((wn * 4) << 6) + lane * 2;

    // Stage 0: msg_W
    {
        const uint4* src = (const uint4*)g_Bp_msg;
#pragma unroll
        for (int it = 0; it < 16; it++) ((uint4*)Bs)[tid + it * 256] = src[tid + it * 256];
        __syncthreads();                       // Ash + Bs ready
        mma_mainloop(A0, Bw, accM);
    }
    // Stage 1: gate_W
    {
        __syncthreads();                       // all warps done with Bs stage 0
        const uint4* src = (const uint4*)g_Bp_gate;
#pragma unroll
        for (int it = 0; it < 16; it++) ((uint4*)Bs)[tid + it * 256] = src[tid + it * 256];
        __syncthreads();
        mma_mainloop(A0, Bw, accG);
    }

    // Epilogue: p = accM * sigmoid(accG), staged through Ash for coalesced out
    __syncthreads();                           // done reading Ash
    {
        const int r = lane >> 2, c2 = (lane & 3) * 2;
#pragma unroll
        for (int mt = 0; mt < 2; mt++)
#pragma unroll
            for (int nt = 0; nt < 4; nt++) {
                int rr  = wm * 32 + mt * 16 + r;
                int col = wn * 32 + nt * 8 + c2;
                float v0 = accM[mt][nt][0] * (1.f / (1.f + __expf(-accG[mt][nt][0])));
                float v1 = accM[mt][nt][1] * (1.f / (1.f + __expf(-accG[mt][nt][1])));
                float v2 = accM[mt][nt][2] * (1.f / (1.f + __expf(-accG[mt][nt][2])));
                float v3 = accM[mt][nt][3] * (1.f / (1.f + __expf(-accG[mt][nt][3])));
                *(float2*)&Ash[rr * 132 + col]       = make_float2(v0, v1);
                *(float2*)&Ash[(rr + 8) * 132 + col] = make_float2(v2, v3);
            }
    }
    __syncthreads();
#pragma unroll
    for (int it = 0; it < 8; it++) {
        int i = tid + it * 256;
        int m = i >> 5, c = i & 31;
        int row = m0 + m;
        if (row < ROWS)
            ((float4*)g_p)[row * 32 + c] = *(float4*)&Ash[m * 132 + c * 4];
    }
}

// ---------------------------------------------------------------------------
// Kernel 2: edge scatter. One warp per edge; both batches.
//   agg[b, tgt] += p[b, src] * rel_emb[rel]
// ---------------------------------------------------------------------------
__global__ __launch_bounds__(256) void edge_scatter_kernel(
    const int* __restrict__ esrc,
    const int* __restrict__ etgt,
    const int* __restrict__ erel,
    const float* __restrict__ rel_emb)
{
    const int gw   = (blockIdx.x * blockDim.x + threadIdx.x) >> 5;
    const int lane = threadIdx.x & 31;
    if (gw >= EE) return;

    const int s = esrc[gw];
    const int t = etgt[gw];
    const int r = erel[gw];

    const float4* R4 = (const float4*)rel_emb;
    const float4  rv = R4[r * 32 + lane];
    const float4* P4 = (const float4*)g_p;

#pragma unroll
    for (int b = 0; b < BB; b++) {
        float4 p = P4[(b * NN + s) * 32 + lane];
        float4 o;
        o.x = p.x * rv.x;
        o.y = p.y * rv.y;
        o.z = p.z * rv.z;
        o.w = p.w * rv.w;
        float* q = &g_agg[((b * NN + t) * 32 + lane) * 4];
        asm volatile("red.global.add.v4.f32 [%0], {%1, %2, %3, %4};"
                     :: "l"(q), "f"(o.x), "f"(o.y), "f"(o.z), "f"(o.w)
                     : "memory");
    }
}

// ---------------------------------------------------------------------------
// Kernel 3: upd = [h | agg] @ update_W + b ; x = h + relu(upd) ; out = LN(x)
// K=256 in two stages of 128 (B chunk staged through smem).
// ---------------------------------------------------------------------------
__global__ __launch_bounds__(256, 2) void update_ln_mma(
    const float* __restrict__ h,
    const float* __restrict__ update_b,
    const float* __restrict__ ln_gamma,
    const float* __restrict__ ln_beta,
    float* __restrict__ out)
{
    extern __shared__ uint32_t sh[];
    float*    Ash = (float*)sh;       // [64][132] (A stage, then X for LN)
    uint32_t* Bs  = sh + ASH_WORDS;   // 16384 words

    const int tid  = threadIdx.x;
    const int m0   = blockIdx.x * 64;
    const int lane = tid & 31, wid = tid >> 5;
    const int wm = wid >> 2, wn = wid & 3;

    float acc[2][4][4];
#pragma unroll
    for (int mt = 0; mt < 2; mt++)
#pragma unroll
        for (int nt = 0; nt < 4; nt++)
#pragma unroll
            for (int q = 0; q < 4; q++) acc[mt][nt][q] = 0.f;

    const float*    A0 = Ash + (wm * 32 + (lane >> 2)) * 132 + (lane & 3);
    const uint32_t* Bw = Bs + ((wn * 4) << 6) + lane * 2;

#pragma unroll
    for (int s = 0; s < 2; s++) {
        if (s) __syncthreads();                // all done reading stage-0 smem
        const uint4* bsrc = (const uint4*)g_Bp_upd + s * 4096;
#pragma unroll
        for (int it = 0; it < 16; it++) ((uint4*)Bs)[tid + it * 256] = bsrc[tid + it * 256];
        fill_A(Ash, (const float4*)(s ? g_agg : h), m0, tid);
        __syncthreads();
        mma_mainloop(A0, Bw, acc);
    }

    // Epilogue: X = relu(acc + bias) -> Ash (residual added in LN pass)
    __syncthreads();
    {
        const int r = lane >> 2, c2 = (lane & 3) * 2;
#pragma unroll
        for (int mt = 0; mt < 2; mt++)
#pragma unroll
            for (int nt = 0; nt < 4; nt++) {
                int rr  = wm * 32 + mt * 16 + r;
                int col = wn * 32 + nt * 8 + c2;
                float b0 = __ldg(&update_b[col]);
                float b1 = __ldg(&update_b[col + 1]);
                float v0 = fmaxf(acc[mt][nt][0] + b0, 0.f);
                float v1 = fmaxf(acc[mt][nt][1] + b1, 0.f);
                float v2 = fmaxf(acc[mt][nt][2] + b0, 0.f);
                float v3 = fmaxf(acc[mt][nt][3] + b1, 0.f);
                *(float2*)&Ash[rr * 132 + col]       = make_float2(v0, v1);
                *(float2*)&Ash[(rr + 8) * 132 + col] = make_float2(v2, v3);
            }
    }
    __syncthreads();

    // LayerNorm: 8 warps x 8 rows; residual h added here (coalesced read)
    {
        const float4 gm = ((const float4*)ln_gamma)[lane];
        const float4 bt = ((const float4*)ln_beta)[lane];
        const float4* h4 = (const float4*)h;
        for (int rr = wid; rr < 64; rr += 8) {
            int row = m0 + rr;
            if (row >= ROWS) continue;
            float4 xv = *(const float4*)&Ash[rr * 132 + lane * 4];
            float4 hv = h4[row * 32 + lane];
            float4 x = make_float4(xv.x + hv.x, xv.y + hv.y,
                                   xv.z + hv.z, xv.w + hv.w);
            float sum = x.x + x.y + x.z + x.w;
            float sq  = x.x * x.x + x.y * x.y + x.z * x.z + x.w * x.w;
#pragma unroll
            for (int off = 16; off; off >>= 1) {
                sum += __shfl_xor_sync(0xffffffffu, sum, off);
                sq  += __shfl_xor_sync(0xffffffffu, sq, off);
            }
            float mu  = sum * (1.f / 128.f);
            float var = sq * (1.f / 128.f) - mu * mu;
            float inv = rsqrtf(var + 1e-5f);
            float4 o;
            o.x = (x.x - mu) * inv * gm.x + bt.x;
            o.y = (x.y - mu) * inv * gm.y + bt.y;
            o.z = (x.z - mu) * inv * gm.z + bt.z;
            o.w = (x.w - mu) * inv * gm.w + bt.w;
            ((float4*)out)[row * 32 + lane] = o;
        }
    }
}

// ---------------------------------------------------------------------------
extern "C" void kernel_launch(void* const* d_in, const int* in_sizes, int n_in,
                              void* d_out, int out_size)
{
    const float* h        = (const float*)d_in[0];
    const int*   esrc     = (const int*)d_in[1];
    const int*   etgt     = (const int*)d_in[2];
    const int*   erel     = (const int*)d_in[3];
    // d_in[4] = nE (== NN, unused)
    const float* msg_W    = (const float*)d_in[5];
    const float* rel_emb  = (const float*)d_in[6];
    const float* gate_W   = (const float*)d_in[7];
    const float* update_W = (const float*)d_in[8];
    const float* update_b = (const float*)d_in[9];
    const float* gamma    = (const float*)d_in[10];
    const float* beta     = (const float*)d_in[11];
    float*       out      = (float*)d_out;

    cudaFuncSetAttribute(node_p_mma,
                         cudaFuncAttributeMaxDynamicSharedMemorySize, GEMM_SMEM);
    cudaFuncSetAttribute(update_ln_mma,
                         cudaFuncAttributeMaxDynamicSharedMemorySize, GEMM_SMEM);

    // Zero the scatter-add target
    void* agg_ptr = nullptr;
    cudaGetSymbolAddress(&agg_ptr, g_agg);
    cudaMemsetAsync(agg_ptr, 0, sizeof(float) * ROWS * DD, 0);

    permute_W_kernel<<<4, 256>>>(msg_W, gate_W, update_W);

    const int mtiles = (ROWS + 63) / 64;   // 1563

    node_p_mma<<<mtiles, 256, GEMM_SMEM>>>(h);

    {
        long long total_threads = (long long)EE * 32;
        int blocks = (int)((total_threads + 255) / 256);   // 62500
        edge_scatter_kernel<<<blocks, 256>>>(esrc, etgt, erel, rel_emb);
    }

    update_ln_mma<<<mtiles, 256, GEMM_SMEM>>>(h, update_b, gamma, beta, out);
}